// round 2
// baseline (speedup 1.0000x reference)
#include <cuda_runtime.h>

#define K_BANDS 36
#define EMBED   128
#define MAXF    130
#define NB_TOT  1025
#define T_LEN   2048
#define B_SZ    8
#define TT      128
#define EPS     1e-5f

// Scratch (allocation-free rule: __device__ globals)
__device__ __align__(16) float g_WgT[K_BANDS * MAXF * EMBED]; // [k][f][e]
__device__ float g_S1[K_BANDS * EMBED];
__device__ float g_S2[K_BANDS * EMBED];

__device__ __forceinline__ void band_params(int k, int& nb, int& start) {
    if (k < 20)      { nb = 16; start = 16 * k; }
    else if (k < 30) { nb = 32; start = 320 + 32 * (k - 20); }
    else if (k < 35) { nb = 64; start = 640 + 64 * (k - 30); }
    else             { nb = 65; start = 960; }
}

// Fold gamma/beta/bias into the GEMM: Wg = W*gamma (transposed to f-major),
// S1[e] = sum_f Wg[e][f], S2[e] = sum_f W[e][f]*beta[f] + b[e].
__global__ void prep_kernel(const float* __restrict__ W,
                            const float* __restrict__ gamma,
                            const float* __restrict__ beta,
                            const float* __restrict__ bias) {
    int k = blockIdx.x;
    int e = threadIdx.x;
    int nb, start; band_params(k, nb, start);
    int f = 2 * nb;
    const float* Wk = W + ((size_t)k * EMBED + e) * MAXF;
    const float* gk = gamma + (size_t)k * MAXF;
    const float* bk = beta  + (size_t)k * MAXF;
    float s1 = 0.f, s2 = 0.f;
    for (int ff = 0; ff < f; ++ff) {
        float w  = Wk[ff];
        float wg = w * gk[ff];
        g_WgT[((size_t)k * MAXF + ff) * EMBED + e] = wg;
        s1 += wg;
        s2 += w * bk[ff];
    }
    g_S1[k * EMBED + e] = s1;
    g_S2[k * EMBED + e] = s2 + bias[k * EMBED + e];
}

// One CTA: band k, batch b, 128 time-steps. GEMM (128t x f) @ (f x 128e)
// with layernorm folded into a cheap epilogue.
__global__ __launch_bounds__(256, 1)
void band_main(const float* __restrict__ spec, float* __restrict__ out) {
    const int k  = 35 - blockIdx.z;          // heavy bands (f=130/128) first
    const int b  = blockIdx.y;
    const int t0 = blockIdx.x * TT;
    int nb, start; band_params(k, nb, start);
    const int f = 2 * nb;

    extern __shared__ float sm[];
    float* xs  = sm;                         // [f][TT]    (f-major)
    float* ws  = sm + MAXF * TT;             // [f][EMBED] (f-major)
    float* smu = ws + MAXF * EMBED;          // [TT]
    float* srs = smu + TT;                   // [TT]

    const int tid = threadIdx.x;

    // ---- Stage x tile: spec[b, start+j, t0+t, c] -> xs[2j+c][t] ----
    const float* sp = spec + (((size_t)b * NB_TOT + start) * T_LEN + t0) * 2;
    const int n4 = nb * (TT / 2);            // one float4 covers (t,t+1)x(re,im)
    for (int idx = tid; idx < n4; idx += 256) {
        int j = idx >> 6;
        int t = (idx & 63) * 2;
        float4 v = *(const float4*)(sp + ((size_t)j * T_LEN + t) * 2);
        // v = (re(t), im(t), re(t+1), im(t+1))
        *(float2*)&xs[(2 * j)     * TT + t] = make_float2(v.x, v.z);
        *(float2*)&xs[(2 * j + 1) * TT + t] = make_float2(v.y, v.w);
    }

    // ---- Stage Wg tile (coalesced float4 copy) ----
    {
        const float4* wsrc = (const float4*)(g_WgT + (size_t)k * MAXF * EMBED);
        float4* wdst = (float4*)ws;
        const int w4 = f * (EMBED / 4);
        for (int idx = tid; idx < w4; idx += 256) wdst[idx] = wsrc[idx];
    }
    __syncthreads();

    // ---- Per-t stats (mean / rstd over f features) ----
    if (tid < TT) {
        float s = 0.f, s2 = 0.f;
        for (int ff = 0; ff < f; ++ff) {
            float v = xs[ff * TT + tid];
            s += v; s2 = fmaf(v, v, s2);
        }
        float inv_f = 1.0f / (float)f;
        float m   = s * inv_f;
        float var = fmaxf(s2 * inv_f - m * m, 0.f);
        smu[tid] = m;
        srs[tid] = rsqrtf(var + EPS);
    }
    __syncthreads();

    // ---- GEMM: 8x8 register tile per thread (16x16 thread grid) ----
    const int ty = tid >> 4, tx = tid & 15;
    const int tr = ty * 8;                   // t offset in tile
    const int ec = tx * 8;                   // e offset

    float acc[8][8];
#pragma unroll
    for (int i = 0; i < 8; ++i)
#pragma unroll
        for (int j = 0; j < 8; ++j) acc[i][j] = 0.f;

    for (int ff = 0; ff < f; ++ff) {
        float4 a0 = *(const float4*)&xs[ff * TT + tr];
        float4 a1 = *(const float4*)&xs[ff * TT + tr + 4];
        float4 b0 = *(const float4*)&ws[ff * EMBED + ec];
        float4 b1 = *(const float4*)&ws[ff * EMBED + ec + 4];
        float av[8] = {a0.x, a0.y, a0.z, a0.w, a1.x, a1.y, a1.z, a1.w};
        float bv[8] = {b0.x, b0.y, b0.z, b0.w, b1.x, b1.y, b1.z, b1.w};
#pragma unroll
        for (int i = 0; i < 8; ++i)
#pragma unroll
            for (int j = 0; j < 8; ++j)
                acc[i][j] = fmaf(av[i], bv[j], acc[i][j]);
    }

    // ---- Epilogue: y = rstd*(G - mu*S1) + S2, store [b][e][k][t] ----
    float muv[8], rsv[8], s1v[8], s2v[8];
#pragma unroll
    for (int i = 0; i < 8; ++i) { muv[i] = smu[tr + i]; rsv[i] = srs[tr + i]; }
#pragma unroll
    for (int j = 0; j < 8; ++j) {
        s1v[j] = g_S1[k * EMBED + ec + j];
        s2v[j] = g_S2[k * EMBED + ec + j];
    }

#pragma unroll
    for (int j = 0; j < 8; ++j) {
        const int e = ec + j;
        float* op = out + ((((size_t)b * EMBED + e) * K_BANDS + k) * T_LEN) + t0 + tr;
        float r[8];
#pragma unroll
        for (int i = 0; i < 8; ++i)
            r[i] = fmaf(rsv[i], acc[i][j] - muv[i] * s1v[j], s2v[j]);
        *(float4*)(op)     = make_float4(r[0], r[1], r[2], r[3]);
        *(float4*)(op + 4) = make_float4(r[4], r[5], r[6], r[7]);
    }
}

extern "C" void kernel_launch(void* const* d_in, const int* in_sizes, int n_in,
                              void* d_out, int out_size) {
    const float* spec  = (const float*)d_in[0];
    const float* gamma = (const float*)d_in[1];
    const float* beta  = (const float*)d_in[2];
    const float* W     = (const float*)d_in[3];
    const float* bias  = (const float*)d_in[4];
    float* out = (float*)d_out;

    prep_kernel<<<K_BANDS, EMBED>>>(W, gamma, beta, bias);

    const size_t smem = (size_t)(MAXF * TT + MAXF * EMBED + 2 * TT) * sizeof(float);
    cudaFuncSetAttribute(band_main, cudaFuncAttributeMaxDynamicSharedMemorySize, (int)smem);
    dim3 grid(T_LEN / TT, B_SZ, K_BANDS);
    band_main<<<grid, 256, smem>>>(spec, out);
}

// round 3
// speedup vs baseline: 1.1533x; 1.1533x over previous
#include <cuda_runtime.h>

#define K_BANDS 36
#define EMBED   128
#define MAXF    130
#define NB_TOT  1025
#define T_LEN   2048
#define B_SZ    8
#define TT      128
#define EPS     1e-5f

typedef unsigned long long u64;

__device__ __align__(16) float g_WgT[K_BANDS * MAXF * EMBED]; // [k][f][e]
__device__ float g_S1[K_BANDS * EMBED];
__device__ float g_S2[K_BANDS * EMBED];

__device__ __forceinline__ void band_params(int k, int& nb, int& start) {
    if (k < 20)      { nb = 16; start = 16 * k; }
    else if (k < 30) { nb = 32; start = 320 + 32 * (k - 20); }
    else if (k < 35) { nb = 64; start = 640 + 64 * (k - 30); }
    else             { nb = 65; start = 960; }
}

__global__ void prep_kernel(const float* __restrict__ W,
                            const float* __restrict__ gamma,
                            const float* __restrict__ beta,
                            const float* __restrict__ bias) {
    int k = blockIdx.x;
    int e = threadIdx.x;
    int nb, start; band_params(k, nb, start);
    int f = 2 * nb;
    const float* Wk = W + ((size_t)k * EMBED + e) * MAXF;
    const float* gk = gamma + (size_t)k * MAXF;
    const float* bk = beta  + (size_t)k * MAXF;
    float s1 = 0.f, s2 = 0.f;
    for (int ff = 0; ff < f; ++ff) {
        float w  = Wk[ff];
        float wg = w * gk[ff];
        g_WgT[((size_t)k * MAXF + ff) * EMBED + e] = wg;
        s1 += wg;
        s2 += w * bk[ff];
    }
    g_S1[k * EMBED + e] = s1;
    g_S2[k * EMBED + e] = s2 + bias[k * EMBED + e];
}

// ---- packed f32x2 helpers ----
__device__ __forceinline__ u64 dup2(float v) {
    u64 r; unsigned x = __float_as_uint(v);
    asm("mov.b64 %0, {%1, %1};" : "=l"(r) : "r"(x));
    return r;
}
__device__ __forceinline__ u64 pack2(float lo, float hi) {
    u64 r;
    asm("mov.b64 %0, {%1, %2};" : "=l"(r) : "r"(__float_as_uint(lo)), "r"(__float_as_uint(hi)));
    return r;
}
__device__ __forceinline__ void fma2(u64& acc, u64 a, u64 b) {
    asm("fma.rn.f32x2 %0, %1, %2, %0;" : "+l"(acc) : "l"(a), "l"(b));
}
__device__ __forceinline__ float2 unpack2(u64 v) {
    unsigned lo, hi;
    asm("mov.b64 {%0, %1}, %2;" : "=r"(lo), "=r"(hi) : "l"(v));
    return make_float2(__uint_as_float(lo), __uint_as_float(hi));
}

__global__ __launch_bounds__(256)
void band_main(const float* __restrict__ spec, float* __restrict__ out) {
    const int k  = 35 - blockIdx.z;          // heavy bands first
    const int b  = blockIdx.y;
    const int t0 = blockIdx.x * TT;
    int nb, start; band_params(k, nb, start);
    const int f = 2 * nb;

    extern __shared__ float sm[];
    float* xs  = sm;                         // [f][TT]
    float* ws  = sm + MAXF * TT;             // [f][EMBED]
    float* smu = ws + MAXF * EMBED;          // [TT]
    float* srs = smu + TT;                   // [TT]

    const int tid = threadIdx.x;

    // ---- Stage x tile ----
    const float* sp = spec + (((size_t)b * NB_TOT + start) * T_LEN + t0) * 2;
    const int n4 = nb * (TT / 2);
    for (int idx = tid; idx < n4; idx += 256) {
        int j = idx >> 6;
        int t = (idx & 63) * 2;
        float4 v = *(const float4*)(sp + ((size_t)j * T_LEN + t) * 2);
        *(float2*)&xs[(2 * j)     * TT + t] = make_float2(v.x, v.z);
        *(float2*)&xs[(2 * j + 1) * TT + t] = make_float2(v.y, v.w);
    }
    __syncthreads();

    // ---- Concurrent: tid<128 stats | tid>=128 W-tile copy ----
    if (tid < TT) {
        float s = 0.f, s2 = 0.f;
        for (int ff = 0; ff < f; ++ff) {
            float v = xs[ff * TT + tid];
            s += v; s2 = fmaf(v, v, s2);
        }
        float inv_f = 1.0f / (float)f;
        float m   = s * inv_f;
        float var = fmaxf(s2 * inv_f - m * m, 0.f);
        smu[tid] = m;
        srs[tid] = rsqrtf(var + EPS);
    } else {
        const float4* wsrc = (const float4*)(g_WgT + (size_t)k * MAXF * EMBED);
        float4* wdst = (float4*)ws;
        const int w4 = f * (EMBED / 4);
        for (int idx = tid - 128; idx < w4; idx += 128) wdst[idx] = wsrc[idx];
    }
    __syncthreads();

    // ---- GEMM: 8t x 8e per thread, packed f32x2 along e ----
    const int ty = tid >> 4, tx = tid & 15;
    const int tr = ty * 8;
    const int ec = tx * 8;

    u64 acc[8][4];
#pragma unroll
    for (int i = 0; i < 8; ++i)
#pragma unroll
        for (int j = 0; j < 4; ++j) acc[i][j] = 0ULL;

    const float* xp = xs + tr;
    const float* wp = ws + ec;

    // f is always even -> unroll by 2
    for (int ff = 0; ff < f; ff += 2) {
        // stream 0
        float4 a00 = *(const float4*)(xp + ff * TT);
        float4 a01 = *(const float4*)(xp + ff * TT + 4);
        float4 b00 = *(const float4*)(wp + ff * EMBED);
        float4 b01 = *(const float4*)(wp + ff * EMBED + 4);
        // stream 1
        float4 a10 = *(const float4*)(xp + (ff + 1) * TT);
        float4 a11 = *(const float4*)(xp + (ff + 1) * TT + 4);
        float4 b10 = *(const float4*)(wp + (ff + 1) * EMBED);
        float4 b11 = *(const float4*)(wp + (ff + 1) * EMBED + 4);

        u64 bb0[4] = { pack2(b00.x, b00.y), pack2(b00.z, b00.w),
                       pack2(b01.x, b01.y), pack2(b01.z, b01.w) };
        u64 bb1[4] = { pack2(b10.x, b10.y), pack2(b10.z, b10.w),
                       pack2(b11.x, b11.y), pack2(b11.z, b11.w) };
        float av0[8] = {a00.x, a00.y, a00.z, a00.w, a01.x, a01.y, a01.z, a01.w};
        float av1[8] = {a10.x, a10.y, a10.z, a10.w, a11.x, a11.y, a11.z, a11.w};

#pragma unroll
        for (int i = 0; i < 8; ++i) {
            u64 ad0 = dup2(av0[i]);
#pragma unroll
            for (int j = 0; j < 4; ++j) fma2(acc[i][j], ad0, bb0[j]);
        }
#pragma unroll
        for (int i = 0; i < 8; ++i) {
            u64 ad1 = dup2(av1[i]);
#pragma unroll
            for (int j = 0; j < 4; ++j) fma2(acc[i][j], ad1, bb1[j]);
        }
    }

    // ---- Epilogue: y = rstd*(G - mu*S1) + S2, layout [b][e][k][t] ----
    float muv[8], rsv[8];
#pragma unroll
    for (int i = 0; i < 8; ++i) { muv[i] = smu[tr + i]; rsv[i] = srs[tr + i]; }
    float s1v[8], s2v[8];
#pragma unroll
    for (int j = 0; j < 8; ++j) {
        s1v[j] = g_S1[k * EMBED + ec + j];
        s2v[j] = g_S2[k * EMBED + ec + j];
    }

#pragma unroll
    for (int j = 0; j < 8; ++j) {
        const int e = ec + j;
        float* op = out + ((((size_t)b * EMBED + e) * K_BANDS + k) * T_LEN) + t0 + tr;
        float r[8];
#pragma unroll
        for (int i = 0; i < 8; ++i) {
            float2 g = unpack2(acc[i][j >> 1]);
            float gij = (j & 1) ? g.y : g.x;
            r[i] = fmaf(rsv[i], gij - muv[i] * s1v[j], s2v[j]);
        }
        *(float4*)(op)     = make_float4(r[0], r[1], r[2], r[3]);
        *(float4*)(op + 4) = make_float4(r[4], r[5], r[6], r[7]);
    }
}

extern "C" void kernel_launch(void* const* d_in, const int* in_sizes, int n_in,
                              void* d_out, int out_size) {
    const float* spec  = (const float*)d_in[0];
    const float* gamma = (const float*)d_in[1];
    const float* beta  = (const float*)d_in[2];
    const float* W     = (const float*)d_in[3];
    const float* bias  = (const float*)d_in[4];
    float* out = (float*)d_out;

    prep_kernel<<<K_BANDS, EMBED>>>(W, gamma, beta, bias);

    const size_t smem = (size_t)(MAXF * TT + MAXF * EMBED + 2 * TT) * sizeof(float);
    cudaFuncSetAttribute(band_main, cudaFuncAttributeMaxDynamicSharedMemorySize, (int)smem);
    dim3 grid(T_LEN / TT, B_SZ, K_BANDS);
    band_main<<<grid, 256, smem>>>(spec, out);
}

// round 4
// speedup vs baseline: 1.2960x; 1.1237x over previous
#include <cuda_runtime.h>

#define K_BANDS 36
#define EMBED   128
#define MAXF    130
#define NB_TOT  1025
#define T_LEN   2048
#define B_SZ    8
#define TT      128
#define CH      16
#define EPS     1e-5f

typedef unsigned long long u64;

__device__ __align__(16) float g_WgT[K_BANDS * MAXF * EMBED]; // [k][f][e]
__device__ float g_S1[K_BANDS * EMBED];
__device__ float g_S2[K_BANDS * EMBED];

__device__ __forceinline__ void band_params(int k, int& nb, int& start) {
    if (k < 20)      { nb = 16; start = 16 * k; }
    else if (k < 30) { nb = 32; start = 320 + 32 * (k - 20); }
    else if (k < 35) { nb = 64; start = 640 + 64 * (k - 30); }
    else             { nb = 65; start = 960; }
}

__global__ void prep_kernel(const float* __restrict__ W,
                            const float* __restrict__ gamma,
                            const float* __restrict__ beta,
                            const float* __restrict__ bias) {
    int k = blockIdx.x;
    int e = threadIdx.x;
    int nb, start; band_params(k, nb, start);
    int f = 2 * nb;
    const float* Wk = W + ((size_t)k * EMBED + e) * MAXF;
    const float* gk = gamma + (size_t)k * MAXF;
    const float* bk = beta  + (size_t)k * MAXF;
    float s1 = 0.f, s2 = 0.f;
    for (int ff = 0; ff < f; ++ff) {
        float w  = Wk[ff];
        float wg = w * gk[ff];
        g_WgT[((size_t)k * MAXF + ff) * EMBED + e] = wg;
        s1 += wg;
        s2 += w * bk[ff];
    }
    g_S1[k * EMBED + e] = s1;
    g_S2[k * EMBED + e] = s2 + bias[k * EMBED + e];
}

// ---- packed f32x2 helpers ----
__device__ __forceinline__ u64 dup2(float v) {
    u64 r; unsigned x = __float_as_uint(v);
    asm("mov.b64 %0, {%1, %1};" : "=l"(r) : "r"(x));
    return r;
}
__device__ __forceinline__ u64 pack2(float lo, float hi) {
    u64 r;
    asm("mov.b64 %0, {%1, %2};" : "=l"(r) : "r"(__float_as_uint(lo)), "r"(__float_as_uint(hi)));
    return r;
}
__device__ __forceinline__ void fma2(u64& acc, u64 a, u64 b) {
    asm("fma.rn.f32x2 %0, %1, %2, %0;" : "+l"(acc) : "l"(a), "l"(b));
}
__device__ __forceinline__ float2 unpack2(u64 v) {
    unsigned lo, hi;
    asm("mov.b64 {%0, %1}, %2;" : "=r"(lo), "=r"(hi) : "l"(v));
    return make_float2(__uint_as_float(lo), __uint_as_float(hi));
}

__device__ __forceinline__ void cp16(unsigned smem_dst, const float* gsrc) {
    asm volatile("cp.async.ca.shared.global [%0], [%1], 16;" :: "r"(smem_dst), "l"(gsrc));
}
__device__ __forceinline__ void cp_commit() {
    asm volatile("cp.async.commit_group;");
}
__device__ __forceinline__ void cp_wait0() {
    asm volatile("cp.async.wait_group 0;");
}

__global__ __launch_bounds__(256, 2)
void band_main(const float* __restrict__ spec, float* __restrict__ out) {
    const int k  = 35 - blockIdx.z;          // heavy bands first
    const int b  = blockIdx.y;
    const int t0 = blockIdx.x * TT;
    int nb, start; band_params(k, nb, start);
    const int f = 2 * nb;

    extern __shared__ float sm[];
    float* xs  = sm;                          // [MAXF][TT]       66.5 KB
    float* wb  = sm + MAXF * TT;              // 2 x [CH][EMBED]  16 KB
    float* smu = wb + 2 * CH * EMBED;         // [TT]
    float* srs = smu + TT;                    // [TT]

    const int tid = threadIdx.x;
    const unsigned wb_s = (unsigned)__cvta_generic_to_shared(wb);
    const float* wsrc = g_WgT + (size_t)k * MAXF * EMBED;
    const int nch = (f + CH - 1) / CH;

    // ---- Issue async load of W chunk 0 ----
    {
        const int clen = (f < CH) ? f : CH;
        const int n4 = clen * (EMBED / 4);
        for (int i = tid; i < n4; i += 256)
            cp16(wb_s + i * 16, wsrc + i * 4);
        cp_commit();
    }

    // ---- Stage x tile ----
    const float* sp = spec + (((size_t)b * NB_TOT + start) * T_LEN + t0) * 2;
    const int n4x = nb * (TT / 2);
    for (int idx = tid; idx < n4x; idx += 256) {
        int j = idx >> 6;
        int t = (idx & 63) * 2;
        float4 v = *(const float4*)(sp + ((size_t)j * T_LEN + t) * 2);
        *(float2*)&xs[(2 * j)     * TT + t] = make_float2(v.x, v.z);
        *(float2*)&xs[(2 * j + 1) * TT + t] = make_float2(v.y, v.w);
    }
    __syncthreads();

    // ---- Stats (tid<128) overlapped with chunk-0 inflight ----
    if (tid < TT) {
        float s = 0.f, s2 = 0.f;
        for (int ff = 0; ff < f; ++ff) {
            float v = xs[ff * TT + tid];
            s += v; s2 = fmaf(v, v, s2);
        }
        float inv_f = 1.0f / (float)f;
        float m   = s * inv_f;
        float var = fmaxf(s2 * inv_f - m * m, 0.f);
        smu[tid] = m;
        srs[tid] = rsqrtf(var + EPS);
    }

    // ---- GEMM over chunks: 8t x 8e per thread, f32x2 along e ----
    const int ty = tid >> 4, tx = tid & 15;
    const int tr = ty * 8;
    const int ec = tx * 8;

    u64 acc[8][4];
#pragma unroll
    for (int i = 0; i < 8; ++i)
#pragma unroll
        for (int j = 0; j < 4; ++j) acc[i][j] = 0ULL;

    for (int c = 0; c < nch; ++c) {
        cp_wait0();
        __syncthreads();                       // chunk c visible; prev buffer free

        if (c + 1 < nch) {                     // prefetch chunk c+1
            const int nb4 = (min(CH, f - (c + 1) * CH)) * (EMBED / 4);
            const unsigned dst = wb_s + ((c + 1) & 1) * (CH * EMBED * 4);
            const float* src = wsrc + (size_t)(c + 1) * CH * EMBED;
            for (int i = tid; i < nb4; i += 256)
                cp16(dst + i * 16, src + i * 4);
        }
        cp_commit();                           // (empty group ok on last iter)

        const int clen = min(CH, f - c * CH);
        const float* wcur  = wb + (c & 1) * (CH * EMBED) + ec;
        const float* xbase = xs + (size_t)c * CH * TT + tr;

#pragma unroll 2
        for (int ffi = 0; ffi < clen; ++ffi) {
            float4 a0 = *(const float4*)(xbase + ffi * TT);
            float4 a1 = *(const float4*)(xbase + ffi * TT + 4);
            float4 b0 = *(const float4*)(wcur + ffi * EMBED);
            float4 b1 = *(const float4*)(wcur + ffi * EMBED + 4);
            u64 bb[4] = { pack2(b0.x, b0.y), pack2(b0.z, b0.w),
                          pack2(b1.x, b1.y), pack2(b1.z, b1.w) };
            float av[8] = {a0.x, a0.y, a0.z, a0.w, a1.x, a1.y, a1.z, a1.w};
#pragma unroll
            for (int i = 0; i < 8; ++i) {
                u64 ad = dup2(av[i]);
#pragma unroll
                for (int j = 0; j < 4; ++j) fma2(acc[i][j], ad, bb[j]);
            }
        }
    }

    // ---- Epilogue: y = rstd*(G - mu*S1) + S2, layout [b][e][k][t] ----
    float muv[8], rsv[8];
#pragma unroll
    for (int i = 0; i < 8; ++i) { muv[i] = smu[tr + i]; rsv[i] = srs[tr + i]; }
    float s1v[8], s2v[8];
#pragma unroll
    for (int j = 0; j < 8; ++j) {
        s1v[j] = g_S1[k * EMBED + ec + j];
        s2v[j] = g_S2[k * EMBED + ec + j];
    }

#pragma unroll
    for (int j = 0; j < 8; ++j) {
        const int e = ec + j;
        float* op = out + ((((size_t)b * EMBED + e) * K_BANDS + k) * T_LEN) + t0 + tr;
        float r[8];
#pragma unroll
        for (int i = 0; i < 8; ++i) {
            float2 g = unpack2(acc[i][j >> 1]);
            float gij = (j & 1) ? g.y : g.x;
            r[i] = fmaf(rsv[i], gij - muv[i] * s1v[j], s2v[j]);
        }
        *(float4*)(op)     = make_float4(r[0], r[1], r[2], r[3]);
        *(float4*)(op + 4) = make_float4(r[4], r[5], r[6], r[7]);
    }
}

extern "C" void kernel_launch(void* const* d_in, const int* in_sizes, int n_in,
                              void* d_out, int out_size) {
    const float* spec  = (const float*)d_in[0];
    const float* gamma = (const float*)d_in[1];
    const float* beta  = (const float*)d_in[2];
    const float* W     = (const float*)d_in[3];
    const float* bias  = (const float*)d_in[4];
    float* out = (float*)d_out;

    prep_kernel<<<K_BANDS, EMBED>>>(W, gamma, beta, bias);

    const size_t smem = (size_t)(MAXF * TT + 2 * CH * EMBED + 2 * TT) * sizeof(float);
    cudaFuncSetAttribute(band_main, cudaFuncAttributeMaxDynamicSharedMemorySize, (int)smem);
    dim3 grid(T_LEN / TT, B_SZ, K_BANDS);
    band_main<<<grid, 256, smem>>>(spec, out);
}

// round 7
// speedup vs baseline: 2.1333x; 1.6461x over previous
#include <cuda_runtime.h>
#include <cuda_bf16.h>
#include <cstdint>

#define K_BANDS 36
#define EMBED   128
#define MAXF    130
#define KPMAX   144
#define NB_TOT  1025
#define T_LEN   2048
#define B_SZ    8
#define TT      128
#define EPS     1e-5f

// ---- device scratch ----
__device__ float g_S1[K_BANDS * EMBED];
__device__ float g_S2[K_BANDS * EMBED];
// Wg hi/lo bf16x2 pairs, [k][e][KPMAX/2] (k-contig per e), zero-padded
__device__ __align__(16) unsigned g_Bh[K_BANDS * EMBED * (KPMAX / 2)];
__device__ __align__(16) unsigned g_Bl[K_BANDS * EMBED * (KPMAX / 2)];

__device__ __forceinline__ void band_params(int k, int& nb, int& start) {
    if (k < 20)      { nb = 16; start = 16 * k; }
    else if (k < 30) { nb = 32; start = 320 + 32 * (k - 20); }
    else if (k < 35) { nb = 64; start = 640 + 64 * (k - 30); }
    else             { nb = 65; start = 960; }
}

__global__ void prep_kernel(const float* __restrict__ W,
                            const float* __restrict__ gamma,
                            const float* __restrict__ beta,
                            const float* __restrict__ bias) {
    int k = blockIdx.x;
    int tid = threadIdx.x;
    int nb, start; band_params(k, nb, start);
    int f = 2 * nb;
    const float* gk = gamma + (size_t)k * MAXF;
    const float* bk = beta  + (size_t)k * MAXF;
    {
        int e = tid;
        const float* Wk = W + ((size_t)k * EMBED + e) * MAXF;
        float s1 = 0.f, s2 = 0.f;
        for (int ff = 0; ff < f; ++ff) {
            float w = Wk[ff];
            s1 += w * gk[ff];
            s2 += w * bk[ff];
        }
        g_S1[k * EMBED + e] = s1;
        g_S2[k * EMBED + e] = s2 + bias[k * EMBED + e];
    }
    for (int idx = tid; idx < EMBED * (KPMAX / 2); idx += EMBED) {
        int e = idx / (KPMAX / 2);
        int p = idx % (KPMAX / 2);
        int k0 = 2 * p, k1 = 2 * p + 1;
        const float* Wk = W + ((size_t)k * EMBED + e) * MAXF;
        float w0 = (k0 < f) ? Wk[k0] * gk[k0] : 0.f;
        float w1 = (k1 < f) ? Wk[k1] * gk[k1] : 0.f;
        __nv_bfloat162 h = __floats2bfloat162_rn(w0, w1);
        float2 hf = __bfloat1622float2(h);
        __nv_bfloat162 l = __floats2bfloat162_rn(w0 - hf.x, w1 - hf.y);
        size_t o = (size_t)k * EMBED * (KPMAX / 2) + idx;
        g_Bh[o] = *(unsigned*)&h;
        g_Bl[o] = *(unsigned*)&l;
    }
}

// ---- ptx helpers (all plain sm_80+ features, no 'a'-gating) ----
__device__ __forceinline__ uint32_t smem_u32(const void* p) {
    uint32_t a;
    asm("{ .reg .u64 t; cvta.to.shared.u64 t, %1; cvt.u32.u64 %0, t; }" : "=r"(a) : "l"(p));
    return a;
}
__device__ __forceinline__ void cp16(uint32_t dst, const void* src) {
    asm volatile("cp.async.ca.shared.global [%0], [%1], 16;" :: "r"(dst), "l"(src));
}
#define CP_COMMIT() asm volatile("cp.async.commit_group;")
#define CP_WAIT0()  asm volatile("cp.async.wait_group 0;")

__device__ __forceinline__ void ldsm_x4(uint32_t* r, uint32_t addr) {
    asm volatile("ldmatrix.sync.aligned.m8n8.x4.shared.b16 {%0,%1,%2,%3}, [%4];"
        : "=r"(r[0]), "=r"(r[1]), "=r"(r[2]), "=r"(r[3]) : "r"(addr));
}
__device__ __forceinline__ void ldsm_x4_t(uint32_t* r, uint32_t addr) {
    asm volatile("ldmatrix.sync.aligned.m8n8.x4.trans.shared.b16 {%0,%1,%2,%3}, [%4];"
        : "=r"(r[0]), "=r"(r[1]), "=r"(r[2]), "=r"(r[3]) : "r"(addr));
}
__device__ __forceinline__ void mma_bf16(float* c, const uint32_t* a, const uint32_t* b) {
    asm volatile("mma.sync.aligned.m16n8k16.row.col.f32.bf16.bf16.f32 "
        "{%0,%1,%2,%3}, {%4,%5,%6,%7}, {%8,%9}, {%0,%1,%2,%3};"
        : "+f"(c[0]), "+f"(c[1]), "+f"(c[2]), "+f"(c[3])
        : "r"(a[0]), "r"(a[1]), "r"(a[2]), "r"(a[3]), "r"(b[0]), "r"(b[1]));
}

// ---- smem byte offsets ----
// A tiles: [k up to 144][t stride 136] bf16
#define SB_A_HI 0
#define SB_A_LO 39168
#define SB_B    78336           // 2 bufs x (hi 6144 + lo 6144); [e][k stride 24]
#define SB_PS   102912          // 2x128 partial sums
#define SB_PS2  103936
#define SB_MU   104960
#define SB_RS   105472
#define SB_S1   105984
#define SB_S2   106496
#define SM_TOT  107008

__global__ __launch_bounds__(256, 2)
void band_main(const float* __restrict__ spec, float* __restrict__ out) {
    const int kb = 35 - blockIdx.z;          // heavy bands first
    const int b  = blockIdx.y;
    const int t0 = blockIdx.x * TT;
    int nb, start; band_params(kb, nb, start);
    const int f    = 2 * nb;
    const int kpad = (f + 15) & ~15;
    const int nch  = kpad >> 4;

    extern __shared__ __align__(16) char smem[];
    const uint32_t sb = smem_u32(smem);
    const int tid = threadIdx.x;
    const int wid = tid >> 5;
    const int lid = tid & 31;

    const unsigned* srcH = g_Bh + (size_t)kb * EMBED * (KPMAX / 2);
    const unsigned* srcL = g_Bl + (size_t)kb * EMBED * (KPMAX / 2);

    // ---- issue B chunk 0 (cp.async) ----
    {
        for (int m = tid; m < 512; m += 256) {
            int typ = m & 1, half = (m >> 1) & 1, e = m >> 2;
            const unsigned* src = (typ ? srcL : srcH) + e * (KPMAX / 2) + half * 4;
            uint32_t dst = sb + SB_B + typ * 6144 + (e * 24 + half * 8) * 2;
            cp16(dst, src);
        }
        CP_COMMIT();
    }

    // ---- stage A: spec -> bf16 hi/lo, [k][t] stride 136 ----
    const float* sp = spec + (((size_t)b * NB_TOT + start) * T_LEN + t0) * 2;
    for (int idx = tid; idx < nb * 64; idx += 256) {
        int j  = idx >> 6;
        int tp = (idx & 63) << 1;
        float4 v = *(const float4*)(sp + ((size_t)j * T_LEN + tp) * 2);
        // k=2j holds (t=tp: v.x, t=tp+1: v.z); k=2j+1 holds (v.y, v.w)
        __nv_bfloat162 h0 = __floats2bfloat162_rn(v.x, v.z);
        float2 h0f = __bfloat1622float2(h0);
        __nv_bfloat162 l0 = __floats2bfloat162_rn(v.x - h0f.x, v.z - h0f.y);
        __nv_bfloat162 h1 = __floats2bfloat162_rn(v.y, v.w);
        float2 h1f = __bfloat1622float2(h1);
        __nv_bfloat162 l1 = __floats2bfloat162_rn(v.y - h1f.x, v.w - h1f.y);
        int o0 = ((2 * j)     * 136 + tp) * 2;
        int o1 = ((2 * j + 1) * 136 + tp) * 2;
        *(__nv_bfloat162*)(smem + SB_A_HI + o0) = h0;
        *(__nv_bfloat162*)(smem + SB_A_LO + o0) = l0;
        *(__nv_bfloat162*)(smem + SB_A_HI + o1) = h1;
        *(__nv_bfloat162*)(smem + SB_A_LO + o1) = l1;
    }
    // zero A pad rows [f, kpad)
    for (int i = tid; i < (kpad - f) * 68; i += 256) {
        int r = f + i / 68, c4 = i % 68;
        *(unsigned*)(smem + SB_A_HI + r * 272 + c4 * 4) = 0u;
        *(unsigned*)(smem + SB_A_LO + r * 272 + c4 * 4) = 0u;
    }
    __syncthreads();

    // ---- stats: split-k over 2 halves of threads ----
    {
        int h = tid >> 7, t = tid & 127;
        float s = 0.f, s2 = 0.f;
        for (int kk = h; kk < f; kk += 2) {
            float hi = __bfloat162float(*(__nv_bfloat16*)(smem + SB_A_HI + (kk * 136 + t) * 2));
            float lo = __bfloat162float(*(__nv_bfloat16*)(smem + SB_A_LO + (kk * 136 + t) * 2));
            float x = hi + lo;
            s += x; s2 = fmaf(x, x, s2);
        }
        ((float*)(smem + SB_PS))[h * 128 + t]  = s;
        ((float*)(smem + SB_PS2))[h * 128 + t] = s2;
    }
    __syncthreads();
    if (tid < 128) {
        int t = tid;
        float s  = ((float*)(smem + SB_PS))[t]  + ((float*)(smem + SB_PS))[128 + t];
        float s2 = ((float*)(smem + SB_PS2))[t] + ((float*)(smem + SB_PS2))[128 + t];
        float inv_f = 1.0f / (float)f;
        float m = s * inv_f;
        float var = fmaxf(s2 * inv_f - m * m, 0.f);
        ((float*)(smem + SB_MU))[t] = m;
        ((float*)(smem + SB_RS))[t] = rsqrtf(var + EPS);
    } else {
        int e = tid - 128;
        ((float*)(smem + SB_S1))[e] = g_S1[kb * EMBED + e];
        ((float*)(smem + SB_S2))[e] = g_S2[kb * EMBED + e];
    }

    // ---- MMA mainloop ----
    const int wm = wid & 3, wn = wid >> 2;
    const int tb = wm * 32, n0 = wn * 64;
    const int lrow  = (lid & 7) + ((lid >> 4) << 3);
    const int lcol8 = ((lid >> 3) & 1) << 3;

    float acc[2][8][4];
#pragma unroll
    for (int m = 0; m < 2; ++m)
#pragma unroll
        for (int g = 0; g < 8; ++g)
#pragma unroll
            for (int q = 0; q < 4; ++q) acc[m][g][q] = 0.f;

    for (int c = 0; c < nch; ++c) {
        CP_WAIT0();
        __syncthreads();
        if (c + 1 < nch) {
            int buf = (c + 1) & 1;
            for (int m = tid; m < 512; m += 256) {
                int typ = m & 1, half = (m >> 1) & 1, e = m >> 2;
                const unsigned* src = (typ ? srcL : srcH) + e * (KPMAX / 2) + (c + 1) * 8 + half * 4;
                uint32_t dst = sb + SB_B + buf * 12288 + typ * 6144 + (e * 24 + half * 8) * 2;
                cp16(dst, src);
            }
        }
        CP_COMMIT();

        const int k0 = c << 4;
        uint32_t ah[2][4], al[2][4];
#pragma unroll
        for (int m = 0; m < 2; ++m) {
            uint32_t ad = sb + SB_A_HI + ((k0 + lrow) * 136 + tb + m * 16 + lcol8) * 2;
            ldsm_x4_t(ah[m], ad);
            ldsm_x4_t(al[m], ad + (SB_A_LO - SB_A_HI));
        }
        const uint32_t bbase = sb + SB_B + (c & 1) * 12288;
#pragma unroll
        for (int g = 0; g < 4; ++g) {
            uint32_t bd = bbase + ((n0 + g * 16 + lrow) * 24 + lcol8) * 2;
            uint32_t bh[4], bl[4];
            ldsm_x4(bh, bd);
            ldsm_x4(bl, bd + 6144);
#pragma unroll
            for (int m = 0; m < 2; ++m) {
                mma_bf16(acc[m][2 * g],     ah[m], bh);
                mma_bf16(acc[m][2 * g + 1], ah[m], bh + 2);
                mma_bf16(acc[m][2 * g],     al[m], bh);
                mma_bf16(acc[m][2 * g + 1], al[m], bh + 2);
                mma_bf16(acc[m][2 * g],     ah[m], bl);
                mma_bf16(acc[m][2 * g + 1], ah[m], bl + 2);
            }
        }
    }

    __syncthreads();   // all A-smem reads done; reuse as out-transpose buffer

    // ---- epilogue: y = rs*(acc - mu*S1) + S2 -> smem [e][132] ----
    {
        float* ob = (float*)smem;
        const float* mus = (const float*)(smem + SB_MU);
        const float* rss = (const float*)(smem + SB_RS);
        const float* s1s = (const float*)(smem + SB_S1);
        const float* s2s = (const float*)(smem + SB_S2);
#pragma unroll
        for (int m = 0; m < 2; ++m) {
            int t1 = tb + m * 16 + (lid >> 2);
            float mu0 = mus[t1],     rs0 = rss[t1];
            float mu1 = mus[t1 + 8], rs1 = rss[t1 + 8];
#pragma unroll
            for (int g = 0; g < 8; ++g) {
                int e0 = n0 + g * 8 + ((lid & 3) << 1);
                float s1a = s1s[e0], s2a = s2s[e0];
                float s1b = s1s[e0 + 1], s2b = s2s[e0 + 1];
                float* a4 = acc[m][g];
                ob[e0 * 132 + t1]           = fmaf(rs0, fmaf(-mu0, s1a, a4[0]), s2a);
                ob[(e0 + 1) * 132 + t1]     = fmaf(rs0, fmaf(-mu0, s1b, a4[1]), s2b);
                ob[e0 * 132 + t1 + 8]       = fmaf(rs1, fmaf(-mu1, s1a, a4[2]), s2a);
                ob[(e0 + 1) * 132 + t1 + 8] = fmaf(rs1, fmaf(-mu1, s1b, a4[3]), s2b);
            }
        }
    }
    __syncthreads();

    // ---- store: warp w -> 16 e-rows, coalesced STG.128 along t ----
    {
        const float* ob = (const float*)smem;
#pragma unroll
        for (int r = 0; r < 16; ++r) {
            int e = wid * 16 + r;
            float4 v = *(const float4*)&ob[e * 132 + lid * 4];
            *(float4*)(out + (((size_t)b * EMBED + e) * K_BANDS + kb) * T_LEN + t0 + lid * 4) = v;
        }
    }
}

extern "C" void kernel_launch(void* const* d_in, const int* in_sizes, int n_in,
                              void* d_out, int out_size) {
    const float* spec  = (const float*)d_in[0];
    const float* gamma = (const float*)d_in[1];
    const float* beta  = (const float*)d_in[2];
    const float* W     = (const float*)d_in[3];
    const float* bias  = (const float*)d_in[4];
    float* out = (float*)d_out;

    prep_kernel<<<K_BANDS, EMBED>>>(W, gamma, beta, bias);

    cudaFuncSetAttribute(band_main, cudaFuncAttributeMaxDynamicSharedMemorySize, SM_TOT);
    dim3 grid(T_LEN / TT, B_SZ, K_BANDS);
    band_main<<<grid, 256, SM_TOT>>>(spec, out);
}

// round 10
// speedup vs baseline: 2.2283x; 1.0446x over previous
#include <cuda_runtime.h>
#include <cuda_bf16.h>
#include <cstdint>

#define K_BANDS 36
#define EMBED   128
#define MAXF    130
#define KPMAX   144
#define NB_TOT  1025
#define T_LEN   2048
#define B_SZ    8
#define TT      128
#define EPS     1e-5f

// ---- device scratch ----
__device__ float g_S1[K_BANDS * EMBED];
__device__ float g_S2[K_BANDS * EMBED];
// Wg hi/lo bf16x2 pairs, [k][e][KPMAX/2] (k-contig per e), zero-padded
__device__ __align__(16) unsigned g_Bh[K_BANDS * EMBED * (KPMAX / 2)];
__device__ __align__(16) unsigned g_Bl[K_BANDS * EMBED * (KPMAX / 2)];

__device__ __forceinline__ void band_params(int k, int& nb, int& start) {
    if (k < 20)      { nb = 16; start = 16 * k; }
    else if (k < 30) { nb = 32; start = 320 + 32 * (k - 20); }
    else if (k < 35) { nb = 64; start = 640 + 64 * (k - 30); }
    else             { nb = 65; start = 960; }
}

// grid (36, 4), 128 threads. blockIdx.y = quarter.
__global__ void prep_kernel(const float* __restrict__ W,
                            const float* __restrict__ gamma,
                            const float* __restrict__ beta,
                            const float* __restrict__ bias) {
    const int k = blockIdx.x, q = blockIdx.y;
    const int tid = threadIdx.x;
    int nb, start; band_params(k, nb, start);
    const int f = 2 * nb;
    const float* gk = gamma + (size_t)k * MAXF;
    const float* bk = beta  + (size_t)k * MAXF;

    // S1/S2: 4 lanes per e, 32 e's per block
    {
        int el = tid >> 2, l = tid & 3;
        int e = q * 32 + el;
        const float* Wk = W + ((size_t)k * EMBED + e) * MAXF;
        float s1 = 0.f, s2 = 0.f;
        for (int ff = l; ff < f; ff += 4) {
            float w = Wk[ff];
            s1 += w * gk[ff];
            s2 += w * bk[ff];
        }
        s1 += __shfl_xor_sync(0xFFFFFFFFu, s1, 1);
        s2 += __shfl_xor_sync(0xFFFFFFFFu, s2, 1);
        s1 += __shfl_xor_sync(0xFFFFFFFFu, s1, 2);
        s2 += __shfl_xor_sync(0xFFFFFFFFu, s2, 2);
        if (l == 0) {
            g_S1[k * EMBED + e] = s1;
            g_S2[k * EMBED + e] = s2 + bias[k * EMBED + e];
        }
    }

    // hi/lo split of Wg, this block handles its quarter of 9216 items
    for (int idx = q * 2304 + tid; idx < (q + 1) * 2304; idx += 128) {
        int e = idx / (KPMAX / 2);
        int p = idx % (KPMAX / 2);
        int k0 = 2 * p, k1 = 2 * p + 1;
        const float* Wk = W + ((size_t)k * EMBED + e) * MAXF;
        float w0 = (k0 < f) ? Wk[k0] * gk[k0] : 0.f;
        float w1 = (k1 < f) ? Wk[k1] * gk[k1] : 0.f;
        __nv_bfloat162 h = __floats2bfloat162_rn(w0, w1);
        float2 hf = __bfloat1622float2(h);
        __nv_bfloat162 l = __floats2bfloat162_rn(w0 - hf.x, w1 - hf.y);
        size_t o = (size_t)k * EMBED * (KPMAX / 2) + idx;
        g_Bh[o] = *(unsigned*)&h;
        g_Bl[o] = *(unsigned*)&l;
    }
}

// ---- ptx helpers (plain sm_80+ features) ----
__device__ __forceinline__ uint32_t smem_u32(const void* p) {
    uint32_t a;
    asm("{ .reg .u64 t; cvta.to.shared.u64 t, %1; cvt.u32.u64 %0, t; }" : "=r"(a) : "l"(p));
    return a;
}
__device__ __forceinline__ void cp16(uint32_t dst, const void* src) {
    asm volatile("cp.async.ca.shared.global [%0], [%1], 16;" :: "r"(dst), "l"(src));
}
#define CP_COMMIT() asm volatile("cp.async.commit_group;")
#define CP_WAIT0()  asm volatile("cp.async.wait_group 0;")

__device__ __forceinline__ void ldsm_x4(uint32_t* r, uint32_t addr) {
    asm volatile("ldmatrix.sync.aligned.m8n8.x4.shared.b16 {%0,%1,%2,%3}, [%4];"
        : "=r"(r[0]), "=r"(r[1]), "=r"(r[2]), "=r"(r[3]) : "r"(addr));
}
__device__ __forceinline__ void ldsm_x4_t(uint32_t* r, uint32_t addr) {
    asm volatile("ldmatrix.sync.aligned.m8n8.x4.trans.shared.b16 {%0,%1,%2,%3}, [%4];"
        : "=r"(r[0]), "=r"(r[1]), "=r"(r[2]), "=r"(r[3]) : "r"(addr));
}
__device__ __forceinline__ void mma_bf16(float* c, const uint32_t* a, const uint32_t* b) {
    asm volatile("mma.sync.aligned.m16n8k16.row.col.f32.bf16.bf16.f32 "
        "{%0,%1,%2,%3}, {%4,%5,%6,%7}, {%8,%9}, {%0,%1,%2,%3};"
        : "+f"(c[0]), "+f"(c[1]), "+f"(c[2]), "+f"(c[3])
        : "r"(a[0]), "r"(a[1]), "r"(a[2]), "r"(a[3]), "r"(b[0]), "r"(b[1]));
}

// ---- smem byte offsets ----
#define SB_A_HI 0
#define SB_A_LO 39168
#define SB_B    78336           // 2 bufs x (hi 6144 + lo 6144); [e][k stride 24]
#define SB_PS   102912
#define SB_PS2  103936
#define SB_MU   104960
#define SB_RS   105472
#define SB_S1   105984
#define SB_S2   106496
#define SM_TOT  107008

__global__ __launch_bounds__(256, 2)
void band_main(const float* __restrict__ spec, float* __restrict__ out) {
    const int kb = 35 - blockIdx.z;          // heavy bands first
    const int b  = blockIdx.y;
    const int t0 = blockIdx.x * TT;
    int nb, start; band_params(kb, nb, start);
    const int f    = 2 * nb;
    const int kpad = (f + 15) & ~15;
    const int nch  = kpad >> 4;

    extern __shared__ __align__(16) char smem[];
    const uint32_t sb = smem_u32(smem);
    const int tid = threadIdx.x;
    const int wid = tid >> 5;
    const int lid = tid & 31;

    const unsigned* srcH = g_Bh + (size_t)kb * EMBED * (KPMAX / 2);
    const unsigned* srcL = g_Bl + (size_t)kb * EMBED * (KPMAX / 2);

    // ---- issue B chunk 0 (cp.async) ----
    {
        for (int m = tid; m < 512; m += 256) {
            int typ = m & 1, half = (m >> 1) & 1, e = m >> 2;
            const unsigned* src = (typ ? srcL : srcH) + e * (KPMAX / 2) + half * 4;
            uint32_t dst = sb + SB_B + typ * 6144 + (e * 24 + half * 8) * 2;
            cp16(dst, src);
        }
        CP_COMMIT();
    }

    // ---- fused stage A + stats: thread owns fixed t, iterates j ----
    {
        const int h = tid >> 7, t = tid & 127;
        const float* sp2 = spec + (((size_t)b * NB_TOT + start) * T_LEN + t0 + t) * 2;
        float s = 0.f, s2 = 0.f;
#pragma unroll 4
        for (int j = h; j < nb; j += 2) {
            float2 v = *(const float2*)(sp2 + (size_t)j * T_LEN * 2);
            float x0 = v.x, x1 = v.y;             // k=2j, k=2j+1
            s += x0 + x1;
            s2 = fmaf(x0, x0, s2);
            s2 = fmaf(x1, x1, s2);
            __nv_bfloat16 h0 = __float2bfloat16(x0);
            __nv_bfloat16 l0 = __float2bfloat16(x0 - __bfloat162float(h0));
            __nv_bfloat16 h1 = __float2bfloat16(x1);
            __nv_bfloat16 l1 = __float2bfloat16(x1 - __bfloat162float(h1));
            int o0 = ((2 * j)     * 136 + t) * 2;
            int o1 = ((2 * j + 1) * 136 + t) * 2;
            *(__nv_bfloat16*)(smem + SB_A_HI + o0) = h0;
            *(__nv_bfloat16*)(smem + SB_A_LO + o0) = l0;
            *(__nv_bfloat16*)(smem + SB_A_HI + o1) = h1;
            *(__nv_bfloat16*)(smem + SB_A_LO + o1) = l1;
        }
        ((float*)(smem + SB_PS))[h * 128 + t]  = s;
        ((float*)(smem + SB_PS2))[h * 128 + t] = s2;
    }
    // zero A pad rows [f, kpad)
    for (int i = tid; i < (kpad - f) * 68; i += 256) {
        int r = f + i / 68, c4 = i % 68;
        *(unsigned*)(smem + SB_A_HI + r * 272 + c4 * 4) = 0u;
        *(unsigned*)(smem + SB_A_LO + r * 272 + c4 * 4) = 0u;
    }
    __syncthreads();

    // ---- finalize stats | stage S1/S2 ----
    if (tid < 128) {
        int t = tid;
        float s  = ((float*)(smem + SB_PS))[t]  + ((float*)(smem + SB_PS))[128 + t];
        float s2 = ((float*)(smem + SB_PS2))[t] + ((float*)(smem + SB_PS2))[128 + t];
        float inv_f = 1.0f / (float)f;
        float m = s * inv_f;
        float var = fmaxf(s2 * inv_f - m * m, 0.f);
        ((float*)(smem + SB_MU))[t] = m;
        ((float*)(smem + SB_RS))[t] = rsqrtf(var + EPS);
    } else {
        int e = tid - 128;
        ((float*)(smem + SB_S1))[e] = g_S1[kb * EMBED + e];
        ((float*)(smem + SB_S2))[e] = g_S2[kb * EMBED + e];
    }

    // ---- MMA mainloop ----
    const int wm = wid & 3, wn = wid >> 2;
    const int tb = wm * 32, n0 = wn * 64;
    const int lrow  = (lid & 7) + ((lid >> 4) << 3);
    const int lcol8 = ((lid >> 3) & 1) << 3;

    float acc[2][8][4];
#pragma unroll
    for (int m = 0; m < 2; ++m)
#pragma unroll
        for (int g = 0; g < 8; ++g)
#pragma unroll
            for (int q = 0; q < 4; ++q) acc[m][g][q] = 0.f;

    for (int c = 0; c < nch; ++c) {
        CP_WAIT0();
        __syncthreads();
        if (c + 1 < nch) {
            int buf = (c + 1) & 1;
            for (int m = tid; m < 512; m += 256) {
                int typ = m & 1, half = (m >> 1) & 1, e = m >> 2;
                const unsigned* src = (typ ? srcL : srcH) + e * (KPMAX / 2) + (c + 1) * 8 + half * 4;
                uint32_t dst = sb + SB_B + buf * 12288 + typ * 6144 + (e * 24 + half * 8) * 2;
                cp16(dst, src);
            }
        }
        CP_COMMIT();

        const int k0 = c << 4;
        uint32_t ah[2][4], al[2][4];
#pragma unroll
        for (int m = 0; m < 2; ++m) {
            uint32_t ad = sb + SB_A_HI + ((k0 + lrow) * 136 + tb + m * 16 + lcol8) * 2;
            ldsm_x4_t(ah[m], ad);
            ldsm_x4_t(al[m], ad + (SB_A_LO - SB_A_HI));
        }
        const uint32_t bbase = sb + SB_B + (c & 1) * 12288;
#pragma unroll
        for (int g = 0; g < 4; ++g) {
            uint32_t bd = bbase + ((n0 + g * 16 + lrow) * 24 + lcol8) * 2;
            uint32_t bh[4], bl[4];
            ldsm_x4(bh, bd);
            ldsm_x4(bl, bd + 6144);
#pragma unroll
            for (int m = 0; m < 2; ++m) {
                mma_bf16(acc[m][2 * g],     ah[m], bh);
                mma_bf16(acc[m][2 * g + 1], ah[m], bh + 2);
                mma_bf16(acc[m][2 * g],     al[m], bh);
                mma_bf16(acc[m][2 * g + 1], al[m], bh + 2);
                mma_bf16(acc[m][2 * g],     ah[m], bl);
                mma_bf16(acc[m][2 * g + 1], ah[m], bl + 2);
            }
        }
    }

    __syncthreads();   // all A-smem reads done; reuse as out-transpose buffer

    // ---- epilogue: y = rs*(acc - mu*S1) + S2 -> smem [e][132] ----
    {
        float* ob = (float*)smem;
        const float* mus = (const float*)(smem + SB_MU);
        const float* rss = (const float*)(smem + SB_RS);
        const float* s1s = (const float*)(smem + SB_S1);
        const float* s2s = (const float*)(smem + SB_S2);
#pragma unroll
        for (int m = 0; m < 2; ++m) {
            int t1 = tb + m * 16 + (lid >> 2);
            float mu0 = mus[t1],     rs0 = rss[t1];
            float mu1 = mus[t1 + 8], rs1 = rss[t1 + 8];
#pragma unroll
            for (int g = 0; g < 8; ++g) {
                int e0 = n0 + g * 8 + ((lid & 3) << 1);
                float s1a = s1s[e0], s2a = s2s[e0];
                float s1b = s1s[e0 + 1], s2b = s2s[e0 + 1];
                float* a4 = acc[m][g];
                ob[e0 * 132 + t1]           = fmaf(rs0, fmaf(-mu0, s1a, a4[0]), s2a);
                ob[(e0 + 1) * 132 + t1]     = fmaf(rs0, fmaf(-mu0, s1b, a4[1]), s2b);
                ob[e0 * 132 + t1 + 8]       = fmaf(rs1, fmaf(-mu1, s1a, a4[2]), s2a);
                ob[(e0 + 1) * 132 + t1 + 8] = fmaf(rs1, fmaf(-mu1, s1b, a4[3]), s2b);
            }
        }
    }
    __syncthreads();

    // ---- store: warp w -> 16 e-rows, coalesced STG.128 along t ----
    {
        const float* ob = (const float*)smem;
#pragma unroll
        for (int r = 0; r < 16; ++r) {
            int e = wid * 16 + r;
            float4 v = *(const float4*)&ob[e * 132 + lid * 4];
            *(float4*)(out + (((size_t)b * EMBED + e) * K_BANDS + kb) * T_LEN + t0 + lid * 4) = v;
        }
    }
}

extern "C" void kernel_launch(void* const* d_in, const int* in_sizes, int n_in,
                              void* d_out, int out_size) {
    const float* spec  = (const float*)d_in[0];
    const float* gamma = (const float*)d_in[1];
    const float* beta  = (const float*)d_in[2];
    const float* W     = (const float*)d_in[3];
    const float* bias  = (const float*)d_in[4];
    float* out = (float*)d_out;

    prep_kernel<<<dim3(K_BANDS, 4), 128>>>(W, gamma, beta, bias);

    cudaFuncSetAttribute(band_main, cudaFuncAttributeMaxDynamicSharedMemorySize, SM_TOT);
    dim3 grid(T_LEN / TT, B_SZ, K_BANDS);
    band_main<<<grid, 256, SM_TOT>>>(spec, out);
}

// round 12
// speedup vs baseline: 2.2793x; 1.0229x over previous
#include <cuda_runtime.h>
#include <cuda_bf16.h>
#include <cstdint>

#define K_BANDS 36
#define EMBED   128
#define MAXF    130
#define KPMAX   144
#define NB_TOT  1025
#define T_LEN   2048
#define B_SZ    8
#define TT      64
#define EPS     1e-5f

// ---- device scratch ----
__device__ float g_S1[K_BANDS * EMBED];
__device__ float g_S2[K_BANDS * EMBED];
// Wg hi/lo bf16x2 pairs, [k][e][KPMAX/2] (k-contig per e), zero-padded
__device__ __align__(16) unsigned g_Bh[K_BANDS * EMBED * (KPMAX / 2)];
__device__ __align__(16) unsigned g_Bl[K_BANDS * EMBED * (KPMAX / 2)];

__device__ __forceinline__ void band_params(int k, int& nb, int& start) {
    if (k < 20)      { nb = 16; start = 16 * k; }
    else if (k < 30) { nb = 32; start = 320 + 32 * (k - 20); }
    else if (k < 35) { nb = 64; start = 640 + 64 * (k - 30); }
    else             { nb = 65; start = 960; }
}

// grid (36, 8), 128 threads.
__global__ void prep_kernel(const float* __restrict__ W,
                            const float* __restrict__ gamma,
                            const float* __restrict__ beta,
                            const float* __restrict__ bias) {
    const int k = blockIdx.x, q = blockIdx.y;
    const int tid = threadIdx.x;
    int nb, start; band_params(k, nb, start);
    const int f = 2 * nb;
    const float* gk = gamma + (size_t)k * MAXF;
    const float* bk = beta  + (size_t)k * MAXF;

    // S1/S2: 8 lanes per e, 16 e's per block
    {
        int el = tid >> 3, l = tid & 7;
        int e = q * 16 + el;
        const float* Wk = W + ((size_t)k * EMBED + e) * MAXF;
        float s1 = 0.f, s2 = 0.f;
        for (int ff = l; ff < f; ff += 8) {
            float w = Wk[ff];
            s1 += w * gk[ff];
            s2 += w * bk[ff];
        }
#pragma unroll
        for (int d = 1; d < 8; d <<= 1) {
            s1 += __shfl_xor_sync(0xFFFFFFFFu, s1, d);
            s2 += __shfl_xor_sync(0xFFFFFFFFu, s2, d);
        }
        if (l == 0) {
            g_S1[k * EMBED + e] = s1;
            g_S2[k * EMBED + e] = s2 + bias[k * EMBED + e];
        }
    }

    // hi/lo split of Wg, this block handles its eighth of 9216 items
    for (int idx = q * 1152 + tid; idx < (q + 1) * 1152; idx += 128) {
        int e = idx / (KPMAX / 2);
        int p = idx % (KPMAX / 2);
        int k0 = 2 * p, k1 = 2 * p + 1;
        const float* Wk = W + ((size_t)k * EMBED + e) * MAXF;
        float w0 = (k0 < f) ? Wk[k0] * gk[k0] : 0.f;
        float w1 = (k1 < f) ? Wk[k1] * gk[k1] : 0.f;
        __nv_bfloat162 h = __floats2bfloat162_rn(w0, w1);
        float2 hf = __bfloat1622float2(h);
        __nv_bfloat162 l = __floats2bfloat162_rn(w0 - hf.x, w1 - hf.y);
        size_t o = (size_t)k * EMBED * (KPMAX / 2) + idx;
        g_Bh[o] = *(unsigned*)&h;
        g_Bl[o] = *(unsigned*)&l;
    }
}

// ---- ptx helpers ----
__device__ __forceinline__ uint32_t smem_u32(const void* p) {
    uint32_t a;
    asm("{ .reg .u64 t; cvta.to.shared.u64 t, %1; cvt.u32.u64 %0, t; }" : "=r"(a) : "l"(p));
    return a;
}
__device__ __forceinline__ void cp16(uint32_t dst, const void* src) {
    asm volatile("cp.async.ca.shared.global [%0], [%1], 16;" :: "r"(dst), "l"(src));
}
#define CP_COMMIT() asm volatile("cp.async.commit_group;")
#define CP_WAIT0()  asm volatile("cp.async.wait_group 0;")

__device__ __forceinline__ void ldsm_x4(uint32_t* r, uint32_t addr) {
    asm volatile("ldmatrix.sync.aligned.m8n8.x4.shared.b16 {%0,%1,%2,%3}, [%4];"
        : "=r"(r[0]), "=r"(r[1]), "=r"(r[2]), "=r"(r[3]) : "r"(addr));
}
__device__ __forceinline__ void ldsm_x4_t(uint32_t* r, uint32_t addr) {
    asm volatile("ldmatrix.sync.aligned.m8n8.x4.trans.shared.b16 {%0,%1,%2,%3}, [%4];"
        : "=r"(r[0]), "=r"(r[1]), "=r"(r[2]), "=r"(r[3]) : "r"(addr));
}
__device__ __forceinline__ void mma_bf16(float* c, const uint32_t* a, const uint32_t* b) {
    asm volatile("mma.sync.aligned.m16n8k16.row.col.f32.bf16.bf16.f32 "
        "{%0,%1,%2,%3}, {%4,%5,%6,%7}, {%8,%9}, {%0,%1,%2,%3};"
        : "+f"(c[0]), "+f"(c[1]), "+f"(c[2]), "+f"(c[3])
        : "r"(a[0]), "r"(a[1]), "r"(a[2]), "r"(a[3]), "r"(b[0]), "r"(b[1]));
}

// ---- smem byte offsets ----
// A: [k<=144][t stride 72] bf16 hi/lo
#define SB_A_HI 0
#define SB_A_LO 20736
#define SB_B    41472          // 2 bufs x (hi 6144 + lo 6144); [e][k stride 24]
#define SB_PS   66048          // 8 x 64 floats
#define SB_PS2  68096
#define SB_MU   70144
#define SB_RS   70400
#define SB_S1   70656
#define SB_S2   71168
#define SM_TOT  71680

__global__ __launch_bounds__(256, 3)
void band_main(const float* __restrict__ spec, float* __restrict__ out) {
    const int kb = 35 - blockIdx.z;          // heavy bands first
    const int b  = blockIdx.y;
    const int t0 = blockIdx.x * TT;
    int nb, start; band_params(kb, nb, start);
    const int f    = 2 * nb;
    const int kpad = (f + 15) & ~15;
    const int nch  = kpad >> 4;

    extern __shared__ __align__(16) char smem[];
    const uint32_t sb = smem_u32(smem);
    const int tid = threadIdx.x;
    const int wid = tid >> 5;
    const int lid = tid & 31;

    const unsigned* srcH = g_Bh + (size_t)kb * EMBED * (KPMAX / 2);
    const unsigned* srcL = g_Bl + (size_t)kb * EMBED * (KPMAX / 2);

    // ---- issue B chunk 0 ----
    {
        for (int m = tid; m < 512; m += 256) {
            int typ = m & 1, half = (m >> 1) & 1, e = m >> 2;
            const unsigned* src = (typ ? srcL : srcH) + e * (KPMAX / 2) + half * 4;
            uint32_t dst = sb + SB_B + typ * 6144 + (e * 24 + half * 8) * 2;
            cp16(dst, src);
        }
        CP_COMMIT();
    }

    // ---- fused stage A + stats: thread owns t-pair, 8-way k split ----
    {
        const int h  = tid >> 5;             // k-group 0..7
        const int t2 = lid * 2;              // t pair base 0..62
        const float* sp4 = spec + (((size_t)b * NB_TOT + start) * T_LEN + t0 + t2) * 2;
        float sA = 0.f, s2A = 0.f, sB = 0.f, s2B = 0.f;
        for (int j = h; j < nb; j += 8) {
            float4 v = *(const float4*)(sp4 + (size_t)j * T_LEN * 2);
            // (k=2j,t2)=v.x (k=2j,t2+1)=v.z (k=2j+1,t2)=v.y (k=2j+1,t2+1)=v.w
            sA += v.x + v.y;  s2A = fmaf(v.x, v.x, s2A); s2A = fmaf(v.y, v.y, s2A);
            sB += v.z + v.w;  s2B = fmaf(v.z, v.z, s2B); s2B = fmaf(v.w, v.w, s2B);
            __nv_bfloat162 h0 = __floats2bfloat162_rn(v.x, v.z);
            float2 h0f = __bfloat1622float2(h0);
            __nv_bfloat162 l0 = __floats2bfloat162_rn(v.x - h0f.x, v.z - h0f.y);
            __nv_bfloat162 h1 = __floats2bfloat162_rn(v.y, v.w);
            float2 h1f = __bfloat1622float2(h1);
            __nv_bfloat162 l1 = __floats2bfloat162_rn(v.y - h1f.x, v.w - h1f.y);
            int o0 = ((2 * j)     * 72 + t2) * 2;
            int o1 = ((2 * j + 1) * 72 + t2) * 2;
            *(__nv_bfloat162*)(smem + SB_A_HI + o0) = h0;
            *(__nv_bfloat162*)(smem + SB_A_LO + o0) = l0;
            *(__nv_bfloat162*)(smem + SB_A_HI + o1) = h1;
            *(__nv_bfloat162*)(smem + SB_A_LO + o1) = l1;
        }
        ((float*)(smem + SB_PS))[h * 64 + t2]      = sA;
        ((float*)(smem + SB_PS))[h * 64 + t2 + 1]  = sB;
        ((float*)(smem + SB_PS2))[h * 64 + t2]     = s2A;
        ((float*)(smem + SB_PS2))[h * 64 + t2 + 1] = s2B;
    }
    // zero A pad rows [f, kpad): 36 u32 per row per buffer
    for (int i = tid; i < (kpad - f) * 36; i += 256) {
        int r = f + i / 36, c4 = i % 36;
        *(unsigned*)(smem + SB_A_HI + r * 144 + c4 * 4) = 0u;
        *(unsigned*)(smem + SB_A_LO + r * 144 + c4 * 4) = 0u;
    }
    __syncthreads();

    // ---- finalize stats | stage S1/S2 ----
    if (tid < 64) {
        int t = tid;
        float s = 0.f, s2 = 0.f;
#pragma unroll
        for (int h = 0; h < 8; ++h) {
            s  += ((float*)(smem + SB_PS))[h * 64 + t];
            s2 += ((float*)(smem + SB_PS2))[h * 64 + t];
        }
        float inv_f = 1.0f / (float)f;
        float m = s * inv_f;
        float var = fmaxf(s2 * inv_f - m * m, 0.f);
        ((float*)(smem + SB_MU))[t] = m;
        ((float*)(smem + SB_RS))[t] = rsqrtf(var + EPS);
    } else if (tid < 192) {
        int e = tid - 64;
        ((float*)(smem + SB_S1))[e] = g_S1[kb * EMBED + e];
        ((float*)(smem + SB_S2))[e] = g_S2[kb * EMBED + e];
    }

    // ---- MMA mainloop: warp tile 32t x 32e (warp grid 2t x 4e) ----
    const int wm = wid & 1, wn = wid >> 1;
    const int tb = wm * 32, n0 = wn * 32;
    const int lrow  = (lid & 7) + ((lid >> 4) << 3);
    const int lcol8 = ((lid >> 3) & 1) << 3;

    float acc[2][4][4];
#pragma unroll
    for (int m = 0; m < 2; ++m)
#pragma unroll
        for (int g = 0; g < 4; ++g)
#pragma unroll
            for (int q = 0; q < 4; ++q) acc[m][g][q] = 0.f;

    for (int c = 0; c < nch; ++c) {
        CP_WAIT0();
        __syncthreads();
        if (c + 1 < nch) {
            int buf = (c + 1) & 1;
            for (int m = tid; m < 512; m += 256) {
                int typ = m & 1, half = (m >> 1) & 1, e = m >> 2;
                const unsigned* src = (typ ? srcL : srcH) + e * (KPMAX / 2) + (c + 1) * 8 + half * 4;
                uint32_t dst = sb + SB_B + buf * 12288 + typ * 6144 + (e * 24 + half * 8) * 2;
                cp16(dst, src);
            }
        }
        CP_COMMIT();

        const int k0 = c << 4;
        uint32_t ah[2][4], al[2][4];
#pragma unroll
        for (int m = 0; m < 2; ++m) {
            uint32_t ad = sb + SB_A_HI + ((k0 + lrow) * 72 + tb + m * 16 + lcol8) * 2;
            ldsm_x4_t(ah[m], ad);
            ldsm_x4_t(al[m], ad + (SB_A_LO - SB_A_HI));
        }
        const uint32_t bbase = sb + SB_B + (c & 1) * 12288;
#pragma unroll
        for (int gg = 0; gg < 2; ++gg) {
            uint32_t bd = bbase + ((n0 + gg * 16 + lrow) * 24 + lcol8) * 2;
            uint32_t bh[4], bl[4];
            ldsm_x4(bh, bd);
            ldsm_x4(bl, bd + 6144);
#pragma unroll
            for (int m = 0; m < 2; ++m) {
                mma_bf16(acc[m][2 * gg],     ah[m], bh);
                mma_bf16(acc[m][2 * gg + 1], ah[m], bh + 2);
                mma_bf16(acc[m][2 * gg],     al[m], bh);
                mma_bf16(acc[m][2 * gg + 1], al[m], bh + 2);
                mma_bf16(acc[m][2 * gg],     ah[m], bl);
                mma_bf16(acc[m][2 * gg + 1], ah[m], bl + 2);
            }
        }
    }

    __syncthreads();   // A reads done; reuse smem base as out buffer [e][68]

    // ---- epilogue: y = rs*(acc - mu*S1) + S2 ----
    {
        float* ob = (float*)smem;
        const float* mus = (const float*)(smem + SB_MU);
        const float* rss = (const float*)(smem + SB_RS);
        const float* s1s = (const float*)(smem + SB_S1);
        const float* s2s = (const float*)(smem + SB_S2);
#pragma unroll
        for (int m = 0; m < 2; ++m) {
            int t1 = tb + m * 16 + (lid >> 2);
            float mu0 = mus[t1],     rs0 = rss[t1];
            float mu1 = mus[t1 + 8], rs1 = rss[t1 + 8];
#pragma unroll
            for (int g = 0; g < 4; ++g) {
                int e0 = n0 + g * 8 + ((lid & 3) << 1);
                float s1a = s1s[e0],     s2a = s2s[e0];
                float s1b = s1s[e0 + 1], s2b = s2s[e0 + 1];
                float* a4 = acc[m][g];
                ob[e0 * 68 + t1]           = fmaf(rs0, fmaf(-mu0, s1a, a4[0]), s2a);
                ob[(e0 + 1) * 68 + t1]     = fmaf(rs0, fmaf(-mu0, s1b, a4[1]), s2b);
                ob[e0 * 68 + t1 + 8]       = fmaf(rs1, fmaf(-mu1, s1a, a4[2]), s2a);
                ob[(e0 + 1) * 68 + t1 + 8] = fmaf(rs1, fmaf(-mu1, s1b, a4[3]), s2b);
            }
        }
    }
    __syncthreads();

    // ---- store: warp covers 2 e-rows per iter, 256B contiguous each ----
    {
        const float* ob = (const float*)smem;
        const int er = lid >> 4, t4 = (lid & 15) * 4;
#pragma unroll
        for (int it = 0; it < 8; ++it) {
            int e = wid * 16 + it * 2 + er;
            float4 v = *(const float4*)&ob[e * 68 + t4];
            *(float4*)(out + (((size_t)b * EMBED + e) * K_BANDS + kb) * T_LEN + t0 + t4) = v;
        }
    }
}

extern "C" void kernel_launch(void* const* d_in, const int* in_sizes, int n_in,
                              void* d_out, int out_size) {
    const float* spec  = (const float*)d_in[0];
    const float* gamma = (const float*)d_in[1];
    const float* beta  = (const float*)d_in[2];
    const float* W     = (const float*)d_in[3];
    const float* bias  = (const float*)d_in[4];
    float* out = (float*)d_out;

    prep_kernel<<<dim3(K_BANDS, 8), 128>>>(W, gamma, beta, bias);

    cudaFuncSetAttribute(band_main, cudaFuncAttributeMaxDynamicSharedMemorySize, SM_TOT);
    dim3 grid(T_LEN / TT, B_SZ, K_BANDS);
    band_main<<<grid, 256, SM_TOT>>>(spec, out);
}